// round 8
// baseline (speedup 1.0000x reference)
#include <cuda_runtime.h>

#define IMG 256
#define NG 1024
#define PIX (1.0f/256.0f)
#define T_TH 1e-4f
#define QCUT 22.0f   // cull: quad > 22 => contribution < alpha*e^-11 (~1.7e-5)

// Sorted + packed per-Gaussian data (device scratch, no allocs)
// g_cull: mx, my, rad2, pad
// g_q:    c00', c01', c11', k'   (c' = -0.5*log2e*invCov, k' = log2(alpha))
// g_c:    cr, cg, cb, pad
__device__ float4 g_cull[NG];
__device__ float4 g_q[NG];
__device__ float4 g_c[NG];

// ---------------------------------------------------------------------------
// Kernel 1: parallel rank sort, 2 threads per Gaussian (16 blocks x 128).
// Each thread of a pair counts over half the array; combined via shfl_xor.
// Even thread precomputes the packed record and scatters to sorted slot.
// ---------------------------------------------------------------------------
__global__ void __launch_bounds__(128) prep_kernel(const float* __restrict__ mean,
                                                   const float* __restrict__ cov,
                                                   const float* __restrict__ color,
                                                   const float* __restrict__ alpha,
                                                   const float* __restrict__ depth) {
    __shared__ float4 sd4[NG/4];
    int tid = threadIdx.x;
    const float4* d4g = (const float4*)depth;
    for (int i = tid; i < NG/4; i += 128) sd4[i] = d4g[i];
    __syncthreads();

    int i    = blockIdx.x*64 + (tid >> 1);   // Gaussian id
    int half = tid & 1;                      // which half of the compare range
    float di = ((const float*)sd4)[i];
    int r0 = 0, r1 = 0, r2 = 0, r3 = 0;
    int j4beg = half * (NG/8);
    #pragma unroll 4
    for (int j4 = j4beg; j4 < j4beg + NG/8; j4++) {
        float4 d = sd4[j4];
        int j = j4*4;
        r0 += (d.x < di) || (d.x == di && (j+0) < i);
        r1 += (d.y < di) || (d.y == di && (j+1) < i);
        r2 += (d.z < di) || (d.z == di && (j+2) < i);
        r3 += (d.w < di) || (d.w == di && (j+3) < i);
    }
    int rpart = (r0 + r1) + (r2 + r3);
    int rank  = rpart + __shfl_xor_sync(0xffffffffu, rpart, 1);

    if (half == 0) {
        float a = cov[i*4+0], b = cov[i*4+1], c = cov[i*4+2], d = cov[i*4+3];
        float det = a*d - b*c;
        const float L2E = 1.4426950408889634f;
        float i00  = d / det;
        float i11  = a / det;
        float ioff = -(b + c) / det;
        float mx = mean[i*2+0], my = mean[i*2+1];
        float bs      = 0.5f*(b + c);
        float half_tr = 0.5f*(a + d);
        float disc    = sqrtf(0.25f*(a - d)*(a - d) + bs*bs);
        float al = alpha[i];
        g_cull[rank] = make_float4(mx, my, QCUT*(half_tr + disc), 0.0f);
        g_q[rank]    = make_float4(-0.5f*L2E*i00, -0.5f*L2E*ioff, -0.5f*L2E*i11,
                                   __log2f(fmaxf(al, 1e-30f)));
        g_c[rank]    = make_float4(color[i*3+0], color[i*3+1], color[i*3+2], 0.0f);
    }
}

// ---------------------------------------------------------------------------
// Kernel 2: 512 threads per 32x16 pixel tile (128 blocks -> one uniform wave).
// One up-front cull+compact (2 Gaussians/thread) of all 1024 sorted Gaussians
// into a contiguous depth-ordered smem list (2 barriers total), padded with
// 8 zero-alpha dummies. Composite: software-pipelined groups of 4.
// ---------------------------------------------------------------------------
__global__ void __launch_bounds__(512) render_kernel(const float* __restrict__ bg,
                                                     const float* __restrict__ topleft,
                                                     float* __restrict__ out) {
    __shared__ float4 sA[NG+8];        // mx, my, c00', c01'
    __shared__ float4 sB[NG+8];        // c11', k', cr, cg
    __shared__ float4 sC4[(NG+8)/4];   // cb, packed 4 per float4
    __shared__ int    sW[16];

    int tid  = threadIdx.x;
    int lane = tid & 31, warp = tid >> 5;

    float tlx = topleft[0], tly = topleft[1];
    float x0 = (blockIdx.x*32 + 0.5f)*PIX - tlx;
    float x1 = (blockIdx.x*32 + 31.5f)*PIX - tlx;
    float y0 = (blockIdx.y*16 + 0.5f)*PIX - tly;
    float y1 = (blockIdx.y*16 + 15.5f)*PIX - tly;

    // ---- cull 2 consecutive ranks per thread ----
    int g0 = tid*2;
    float4 cu0 = g_cull[g0+0];
    float4 cu1 = g_cull[g0+1];
    unsigned m = 0;
    {
        float cx, cy;
        cx = fminf(fmaxf(cu0.x, x0), x1) - cu0.x;
        cy = fminf(fmaxf(cu0.y, y0), y1) - cu0.y;
        if (cx*cx + cy*cy <= cu0.z) m |= 1u;
        cx = fminf(fmaxf(cu1.x, x0), x1) - cu1.x;
        cy = fminf(fmaxf(cu1.y, y0), y1) - cu1.y;
        if (cx*cx + cy*cy <= cu1.z) m |= 2u;
    }
    int cnt = __popc(m);
    int scan = cnt;
    #pragma unroll
    for (int d = 1; d < 32; d <<= 1) {
        int v = __shfl_up_sync(0xffffffffu, scan, d);
        if (lane >= d) scan += v;
    }
    if (lane == 31) sW[warp] = scan;
    __syncthreads();                         // barrier 1: warp totals
    int4 wv0 = *(const int4*)&sW[0];
    int4 wv1 = *(const int4*)&sW[4];
    int4 wv2 = *(const int4*)&sW[8];
    int4 wv3 = *(const int4*)&sW[12];
    int ntot = (wv0.x + wv0.y + wv0.z + wv0.w) + (wv1.x + wv1.y + wv1.z + wv1.w)
             + (wv2.x + wv2.y + wv2.z + wv2.w) + (wv3.x + wv3.y + wv3.z + wv3.w);
    int base = 0;
    {
        const int* wS = &sW[0];
        #pragma unroll
        for (int w = 0; w < 15; w++) if (w < warp) base += wS[w];
    }
    int pos = base + (scan - cnt);
    #pragma unroll
    for (int u = 0; u < 2; u++) {
        if (m & (1u << u)) {
            float4 cu = (u == 0) ? cu0 : cu1;
            float4 qv = g_q[g0+u];
            float4 cv = g_c[g0+u];
            sA[pos] = make_float4(cu.x, cu.y, qv.x, qv.y);
            sB[pos] = make_float4(qv.z, qv.w, cv.x, cv.y);
            ((float*)sC4)[pos] = cv.z;
            pos++;
        }
    }
    if (tid < 8) {                           // 8 zero-alpha dummies (exact no-op)
        sA[ntot+tid] = make_float4(0.f, 0.f, 0.f, 0.f);
        sB[ntot+tid] = make_float4(0.f, -1e30f, 0.f, 0.f);
        ((float*)sC4)[ntot+tid] = 0.f;
    }
    __syncthreads();                         // barrier 2: list published
    int n = (ntot + 3) & ~3;

    // ---- composite: pipelined groups of 4, no barriers, early break ----
    int tx = tid & 31, ty = tid >> 5;
    float px = (blockIdx.x*32 + tx + 0.5f)*PIX - tlx;
    float py = (blockIdx.y*16 + ty + 0.5f)*PIX - tly;
    int pi = ((blockIdx.y*16 + ty)*IMG + blockIdx.x*32 + tx)*3;
    float bgr = bg[pi+0], bgg = bg[pi+1], bgb = bg[pi+2];

    float T = 1.0f, cr = 0.0f, cg = 0.0f, cb = 0.0f;

    float4 A0 = sA[0], A1 = sA[1], A2 = sA[2], A3 = sA[3];
    float4 B0 = sB[0], B1 = sB[1], B2 = sB[2], B3 = sB[3];
    float4 Cv = sC4[0];

    #pragma unroll 2
    for (int i = 0; i < n; i += 4) {
        // prefetch next group (always in-bounds: 8 dummies past ntot)
        float4 nA0 = sA[i+4], nA1 = sA[i+5], nA2 = sA[i+6], nA3 = sA[i+7];
        float4 nB0 = sB[i+4], nB1 = sB[i+5], nB2 = sB[i+6], nB3 = sB[i+7];
        float4 nCv = sC4[i/4 + 1];

        float ax[4];
        {
            float dx, dy, qd;
            dx = px - A0.x; dy = py - A0.y;
            qd = dx*(A0.z*dx + A0.w*dy) + (B0.x*dy*dy + B0.y);
            ax[0] = fminf(exp2f(qd), 0.99f);
            dx = px - A1.x; dy = py - A1.y;
            qd = dx*(A1.z*dx + A1.w*dy) + (B1.x*dy*dy + B1.y);
            ax[1] = fminf(exp2f(qd), 0.99f);
            dx = px - A2.x; dy = py - A2.y;
            qd = dx*(A2.z*dx + A2.w*dy) + (B2.x*dy*dy + B2.y);
            ax[2] = fminf(exp2f(qd), 0.99f);
            dx = px - A3.x; dy = py - A3.y;
            qd = dx*(A3.z*dx + A3.w*dy) + (B3.x*dy*dy + B3.y);
            ax[3] = fminf(exp2f(qd), 0.99f);
        }
        float q0 = 1.0f-ax[0], q1 = 1.0f-ax[1], q2 = 1.0f-ax[2], q3 = 1.0f-ax[3];
        float p2 = q0*q1;
        float Tn = T * (p2*(q2*q3));
        if (Tn > T_TH) {
            // fast path: all four steps provably active (T monotone decreasing)
            float t0 = T, t1 = T*q0, t2 = T*p2, t3 = t2*q2;
            float w0v = ax[0]*t0, w1v = ax[1]*t1, w2v = ax[2]*t2, w3v = ax[3]*t3;
            cr = fmaf(w0v, B0.z, cr); cg = fmaf(w0v, B0.w, cg); cb = fmaf(w0v, Cv.x, cb);
            cr = fmaf(w1v, B1.z, cr); cg = fmaf(w1v, B1.w, cg); cb = fmaf(w1v, Cv.y, cb);
            cr = fmaf(w2v, B2.z, cr); cg = fmaf(w2v, B2.w, cg); cb = fmaf(w2v, Cv.z, cb);
            cr = fmaf(w3v, B3.z, cr); cg = fmaf(w3v, B3.w, cg); cb = fmaf(w3v, Cv.w, cb);
            T = Tn;
        } else {
            // crossing group: exact masked sequential (runs at most once)
            float rr[4] = {B0.z, B1.z, B2.z, B3.z};
            float gg[4] = {B0.w, B1.w, B2.w, B3.w};
            float bb[4] = {Cv.x, Cv.y, Cv.z, Cv.w};
            #pragma unroll
            for (int u = 0; u < 4; u++) {
                if (T > T_TH) {
                    float w = ax[u] * T;
                    cr = fmaf(w, rr[u], cr);
                    cg = fmaf(w, gg[u], cg);
                    cb = fmaf(w, bb[u], cb);
                    T *= (1.0f - ax[u]);
                }
            }
            if (T <= T_TH) break;
        }
        A0 = nA0; A1 = nA1; A2 = nA2; A3 = nA3;
        B0 = nB0; B1 = nB1; B2 = nB2; B3 = nB3;
        Cv = nCv;
    }

    out[pi+0] = cr + T*bgr;
    out[pi+1] = cg + T*bgg;
    out[pi+2] = cb + T*bgb;
}

extern "C" void kernel_launch(void* const* d_in, const int* in_sizes, int n_in,
                              void* d_out, int out_size) {
    const float* mean    = (const float*)d_in[0];
    const float* cov     = (const float*)d_in[1];
    const float* color   = (const float*)d_in[2];
    const float* alpha   = (const float*)d_in[3];
    const float* depth   = (const float*)d_in[4];
    const float* bg      = (const float*)d_in[5];
    const float* topleft = (const float*)d_in[6];

    prep_kernel<<<16, 128>>>(mean, cov, color, alpha, depth);
    dim3 grid(IMG/32, IMG/16), block(512);
    render_kernel<<<grid, block>>>(bg, topleft, (float*)d_out);
}

// round 9
// speedup vs baseline: 1.1086x; 1.1086x over previous
#include <cuda_runtime.h>

#define IMG 256
#define NG 1024
#define PIX (1.0f/256.0f)
#define T_TH 1e-4f
#define QCUT 18.0f   // cull: quad > 18 => contribution < alpha*e^-9 (~1.2e-4)
#define NBLK 128     // 8 x 16 tiles of 32x16 px; <= 148 SMs -> all resident

// Sorted + packed per-Gaussian data (device scratch, no allocs)
__device__ float4 g_cull[NG];  // mx, my, rad2, pad
__device__ float4 g_q[NG];     // c00', c01', c11', k'
__device__ float4 g_c[NG];     // cr, cg, cb, pad
__device__ unsigned long long g_bar;   // monotonic barrier counter (zero-init)

// ---------------------------------------------------------------------------
// Single fused kernel: 128 blocks x 512 threads, all resident in one wave.
// Phase 0: each block preps 8 Gaussians (rank sort + packed record), then a
//          device-wide barrier (monotonic epoch counter -> graph-replay safe).
// Phase 1: per-tile cull+compact of all 1024 sorted Gaussians (2 per thread).
// Phase 2: per-pixel front-to-back composite, pipelined groups of 4.
// ---------------------------------------------------------------------------
__global__ void __launch_bounds__(512) fused_kernel(const float* __restrict__ mean,
                                                    const float* __restrict__ cov,
                                                    const float* __restrict__ color,
                                                    const float* __restrict__ alpha,
                                                    const float* __restrict__ depth,
                                                    const float* __restrict__ bg,
                                                    const float* __restrict__ topleft,
                                                    float* __restrict__ out) {
    __shared__ float4 sA[NG+8];        // mx, my, c00', c01'  (aliased by depths in phase 0)
    __shared__ float4 sB[NG+8];        // c11', k', cr, cg
    __shared__ float4 sC4[(NG+8)/4];   // cb, packed
    __shared__ int    sW[16];
    __shared__ int    sRank[8];

    int tid  = threadIdx.x;
    int lane = tid & 31, warp = tid >> 5;

    // ================= Phase 0: prep (8 Gaussians per block) =================
    {
        float4* sd4 = (float4*)sA;              // alias: 1024 depths = 4KB
        const float4* d4g = (const float4*)depth;
        if (tid < 256) sd4[tid] = d4g[tid];
        if (tid < 8)   sRank[tid] = 0;
        __syncthreads();

        int sub = tid >> 6;                     // 0..7 (64 threads per Gaussian)
        int gi  = blockIdx.x*8 + sub;
        float di = ((const float*)sd4)[gi];
        int lo4 = (tid & 63) * 4;               // 16 floats per thread
        int r = 0;
        #pragma unroll
        for (int j4 = 0; j4 < 4; j4++) {
            float4 d = sd4[lo4 + j4];
            int j = (lo4 + j4) * 4;
            r += (d.x < di) || (d.x == di && (j+0) < gi);
            r += (d.y < di) || (d.y == di && (j+1) < gi);
            r += (d.z < di) || (d.z == di && (j+2) < gi);
            r += (d.w < di) || (d.w == di && (j+3) < gi);
        }
        #pragma unroll
        for (int s = 16; s; s >>= 1) r += __shfl_xor_sync(0xffffffffu, r, s);
        if (lane == 0) atomicAdd(&sRank[sub], r);
        __syncthreads();

        if ((tid & 63) == 0) {
            int rank = sRank[sub];
            float a = cov[gi*4+0], b = cov[gi*4+1], c = cov[gi*4+2], d = cov[gi*4+3];
            float det = a*d - b*c;
            const float L2E = 1.4426950408889634f;
            float i00  = d / det;
            float i11  = a / det;
            float ioff = -(b + c) / det;
            float mx = mean[gi*2+0], my = mean[gi*2+1];
            float bs      = 0.5f*(b + c);
            float half_tr = 0.5f*(a + d);
            float disc    = sqrtf(0.25f*(a - d)*(a - d) + bs*bs);
            float al = alpha[gi];
            g_cull[rank] = make_float4(mx, my, QCUT*(half_tr + disc), 0.0f);
            g_q[rank]    = make_float4(-0.5f*L2E*i00, -0.5f*L2E*ioff, -0.5f*L2E*i11,
                                       __log2f(fmaxf(al, 1e-30f)));
            g_c[rank]    = make_float4(color[gi*3+0], color[gi*3+1], color[gi*3+2], 0.0f);
            __threadfence();                    // release this Gaussian's record
        }
        __syncthreads();

        // device-wide barrier: monotonic epoch counter (replay-safe, all blocks
        // resident in one wave so spinning cannot deadlock)
        if (tid == 0) {
            unsigned long long ticket = atomicAdd(&g_bar, 1ULL);
            unsigned long long target = (ticket/NBLK + 1ULL) * NBLK;
            while (*(volatile unsigned long long*)&g_bar < target) __nanosleep(64);
        }
        __syncthreads();
        __threadfence();                        // acquire all blocks' records
    }

    // ================= Phase 1: cull + compact (2 Gaussians/thread) ==========
    int bx = blockIdx.x & 7, by = blockIdx.x >> 3;
    float tlx = topleft[0], tly = topleft[1];
    float x0 = (bx*32 + 0.5f)*PIX - tlx;
    float x1 = (bx*32 + 31.5f)*PIX - tlx;
    float y0 = (by*16 + 0.5f)*PIX - tly;
    float y1 = (by*16 + 15.5f)*PIX - tly;

    int g0 = tid*2;
    float4 cu0 = g_cull[g0+0];
    float4 cu1 = g_cull[g0+1];
    unsigned m = 0;
    {
        float cx, cy;
        cx = fminf(fmaxf(cu0.x, x0), x1) - cu0.x;
        cy = fminf(fmaxf(cu0.y, y0), y1) - cu0.y;
        if (cx*cx + cy*cy <= cu0.z) m |= 1u;
        cx = fminf(fmaxf(cu1.x, x0), x1) - cu1.x;
        cy = fminf(fmaxf(cu1.y, y0), y1) - cu1.y;
        if (cx*cx + cy*cy <= cu1.z) m |= 2u;
    }
    int cnt = __popc(m);
    int scan = cnt;
    #pragma unroll
    for (int d = 1; d < 32; d <<= 1) {
        int v = __shfl_up_sync(0xffffffffu, scan, d);
        if (lane >= d) scan += v;
    }
    if (lane == 31) sW[warp] = scan;
    __syncthreads();                             // warp totals
    int ntot = 0;
    {
        #pragma unroll
        for (int w = 0; w < 16; w++) ntot += sW[w];
    }
    int base = 0;
    #pragma unroll
    for (int w = 0; w < 15; w++) if (w < warp) base += sW[w];
    int pos = base + (scan - cnt);
    #pragma unroll
    for (int u = 0; u < 2; u++) {
        if (m & (1u << u)) {
            float4 cu = (u == 0) ? cu0 : cu1;
            float4 qv = g_q[g0+u];
            float4 cv = g_c[g0+u];
            sA[pos] = make_float4(cu.x, cu.y, qv.x, qv.y);
            sB[pos] = make_float4(qv.z, qv.w, cv.x, cv.y);
            ((float*)sC4)[pos] = cv.z;
            pos++;
        }
    }
    if (tid < 8) {                               // zero-alpha dummies (exact no-op)
        sA[ntot+tid] = make_float4(0.f, 0.f, 0.f, 0.f);
        sB[ntot+tid] = make_float4(0.f, -1e30f, 0.f, 0.f);
        ((float*)sC4)[ntot+tid] = 0.f;
    }
    __syncthreads();                             // list published
    int n = (ntot + 3) & ~3;

    // ================= Phase 2: composite (pipelined groups of 4) ============
    int tx = tid & 31, ty = tid >> 5;
    float px = (bx*32 + tx + 0.5f)*PIX - tlx;
    float py = (by*16 + ty + 0.5f)*PIX - tly;
    int pi = ((by*16 + ty)*IMG + bx*32 + tx)*3;
    float bgr = bg[pi+0], bgg = bg[pi+1], bgb = bg[pi+2];

    float T = 1.0f, cr = 0.0f, cg = 0.0f, cb = 0.0f;

    float4 A0 = sA[0], A1 = sA[1], A2 = sA[2], A3 = sA[3];
    float4 B0 = sB[0], B1 = sB[1], B2 = sB[2], B3 = sB[3];
    float4 Cv = sC4[0];

    #pragma unroll 2
    for (int i = 0; i < n; i += 4) {
        float4 nA0 = sA[i+4], nA1 = sA[i+5], nA2 = sA[i+6], nA3 = sA[i+7];
        float4 nB0 = sB[i+4], nB1 = sB[i+5], nB2 = sB[i+6], nB3 = sB[i+7];
        float4 nCv = sC4[i/4 + 1];

        float ax[4];
        {
            float dx, dy, qd;
            dx = px - A0.x; dy = py - A0.y;
            qd = dx*(A0.z*dx + A0.w*dy) + (B0.x*dy*dy + B0.y);
            ax[0] = fminf(exp2f(qd), 0.99f);
            dx = px - A1.x; dy = py - A1.y;
            qd = dx*(A1.z*dx + A1.w*dy) + (B1.x*dy*dy + B1.y);
            ax[1] = fminf(exp2f(qd), 0.99f);
            dx = px - A2.x; dy = py - A2.y;
            qd = dx*(A2.z*dx + A2.w*dy) + (B2.x*dy*dy + B2.y);
            ax[2] = fminf(exp2f(qd), 0.99f);
            dx = px - A3.x; dy = py - A3.y;
            qd = dx*(A3.z*dx + A3.w*dy) + (B3.x*dy*dy + B3.y);
            ax[3] = fminf(exp2f(qd), 0.99f);
        }
        float q0 = 1.0f-ax[0], q1 = 1.0f-ax[1], q2 = 1.0f-ax[2], q3 = 1.0f-ax[3];
        float p2 = q0*q1;
        float Tn = T * (p2*(q2*q3));
        if (Tn > T_TH) {
            float t0 = T, t1 = T*q0, t2 = T*p2, t3 = t2*q2;
            float w0v = ax[0]*t0, w1v = ax[1]*t1, w2v = ax[2]*t2, w3v = ax[3]*t3;
            cr = fmaf(w0v, B0.z, cr); cg = fmaf(w0v, B0.w, cg); cb = fmaf(w0v, Cv.x, cb);
            cr = fmaf(w1v, B1.z, cr); cg = fmaf(w1v, B1.w, cg); cb = fmaf(w1v, Cv.y, cb);
            cr = fmaf(w2v, B2.z, cr); cg = fmaf(w2v, B2.w, cg); cb = fmaf(w2v, Cv.z, cb);
            cr = fmaf(w3v, B3.z, cr); cg = fmaf(w3v, B3.w, cg); cb = fmaf(w3v, Cv.w, cb);
            T = Tn;
        } else {
            // crossing group: exact masked sequential (runs at most once)
            float rr[4] = {B0.z, B1.z, B2.z, B3.z};
            float gg[4] = {B0.w, B1.w, B2.w, B3.w};
            float bb[4] = {Cv.x, Cv.y, Cv.z, Cv.w};
            #pragma unroll
            for (int u = 0; u < 4; u++) {
                if (T > T_TH) {
                    float w = ax[u] * T;
                    cr = fmaf(w, rr[u], cr);
                    cg = fmaf(w, gg[u], cg);
                    cb = fmaf(w, bb[u], cb);
                    T *= (1.0f - ax[u]);
                }
            }
            if (T <= T_TH) break;
        }
        A0 = nA0; A1 = nA1; A2 = nA2; A3 = nA3;
        B0 = nB0; B1 = nB1; B2 = nB2; B3 = nB3;
        Cv = nCv;
    }

    out[pi+0] = cr + T*bgr;
    out[pi+1] = cg + T*bgg;
    out[pi+2] = cb + T*bgb;
}

extern "C" void kernel_launch(void* const* d_in, const int* in_sizes, int n_in,
                              void* d_out, int out_size) {
    const float* mean    = (const float*)d_in[0];
    const float* cov     = (const float*)d_in[1];
    const float* color   = (const float*)d_in[2];
    const float* alpha   = (const float*)d_in[3];
    const float* depth   = (const float*)d_in[4];
    const float* bg      = (const float*)d_in[5];
    const float* topleft = (const float*)d_in[6];

    fused_kernel<<<NBLK, 512>>>(mean, cov, color, alpha, depth,
                                bg, topleft, (float*)d_out);
}

// round 10
// speedup vs baseline: 1.3920x; 1.2557x over previous
#include <cuda_runtime.h>

#define IMG 256
#define NG 1024
#define PIX (1.0f/256.0f)
#define T_TH 1e-4f
#define QCUT 12.0f   // cull: quad > 12 => contribution < alpha*e^-6 (~2.5e-3 peak, boundary-only)
#define NBLK 128     // 8 x 16 tiles of 32x16 px; <= 148 SMs -> all resident

// Sorted + packed per-Gaussian data (device scratch, no allocs)
__device__ float4 g_cull[NG];  // mx, my, rad2, pad
__device__ float4 g_q[NG];     // c00', c01', c11', k'
__device__ float4 g_c[NG];     // cr, cg, cb, pad
__device__ unsigned long long g_bar;   // monotonic barrier counter (zero-init)

// ---------------------------------------------------------------------------
// Single fused kernel: 128 blocks x 512 threads, all resident in one wave.
// Phase 0: each block preps 8 Gaussians (rank sort + packed record), then a
//          device-wide barrier (monotonic epoch counter -> graph-replay safe;
//          release = writer fence + atomic, acquire = ld.acquire spin).
// Phase 1: per-tile cull+compact of all 1024 sorted Gaussians (2 per thread).
// Phase 2: per-pixel front-to-back composite, pipelined groups of 4.
// ---------------------------------------------------------------------------
__global__ void __launch_bounds__(512) fused_kernel(const float* __restrict__ mean,
                                                    const float* __restrict__ cov,
                                                    const float* __restrict__ color,
                                                    const float* __restrict__ alpha,
                                                    const float* __restrict__ depth,
                                                    const float* __restrict__ bg,
                                                    const float* __restrict__ topleft,
                                                    float* __restrict__ out) {
    __shared__ float4 sA[NG+8];        // mx, my, c00', c01'  (aliased by depths in phase 0)
    __shared__ float4 sB[NG+8];        // c11', k', cr, cg
    __shared__ float4 sC4[(NG+8)/4];   // cb, packed
    __shared__ int    sW[16];
    __shared__ int    sRank[8];

    int tid  = threadIdx.x;
    int lane = tid & 31, warp = tid >> 5;

    // tile geometry + background prefetch (hides under barrier wait)
    int bx = blockIdx.x & 7, by = blockIdx.x >> 3;
    float tlx = topleft[0], tly = topleft[1];
    int tx = tid & 31, ty = tid >> 5;
    int pi = ((by*16 + ty)*IMG + bx*32 + tx)*3;
    float bgr = bg[pi+0], bgg = bg[pi+1], bgb = bg[pi+2];

    // ================= Phase 0: prep (8 Gaussians per block) =================
    {
        float4* sd4 = (float4*)sA;              // alias: 1024 depths = 4KB
        const float4* d4g = (const float4*)depth;
        if (tid < 256) sd4[tid] = d4g[tid];
        if (tid < 8)   sRank[tid] = 0;
        __syncthreads();

        int sub = tid >> 6;                     // 0..7 (64 threads per Gaussian)
        int gi  = blockIdx.x*8 + sub;
        float di = ((const float*)sd4)[gi];
        int lo4 = (tid & 63) * 4;               // 16 floats per thread
        int r = 0;
        #pragma unroll
        for (int j4 = 0; j4 < 4; j4++) {
            float4 d = sd4[lo4 + j4];
            int j = (lo4 + j4) * 4;
            r += (d.x < di) || (d.x == di && (j+0) < gi);
            r += (d.y < di) || (d.y == di && (j+1) < gi);
            r += (d.z < di) || (d.z == di && (j+2) < gi);
            r += (d.w < di) || (d.w == di && (j+3) < gi);
        }
        #pragma unroll
        for (int s = 16; s; s >>= 1) r += __shfl_xor_sync(0xffffffffu, r, s);
        if (lane == 0) atomicAdd(&sRank[sub], r);
        __syncthreads();

        if ((tid & 63) == 0) {
            int rank = sRank[sub];
            float a = cov[gi*4+0], b = cov[gi*4+1], c = cov[gi*4+2], d = cov[gi*4+3];
            float det = a*d - b*c;
            const float L2E = 1.4426950408889634f;
            float i00  = d / det;
            float i11  = a / det;
            float ioff = -(b + c) / det;
            float mx = mean[gi*2+0], my = mean[gi*2+1];
            float bs      = 0.5f*(b + c);
            float half_tr = 0.5f*(a + d);
            float disc    = sqrtf(0.25f*(a - d)*(a - d) + bs*bs);
            float al = alpha[gi];
            g_cull[rank] = make_float4(mx, my, QCUT*(half_tr + disc), 0.0f);
            g_q[rank]    = make_float4(-0.5f*L2E*i00, -0.5f*L2E*ioff, -0.5f*L2E*i11,
                                       __log2f(fmaxf(al, 1e-30f)));
            g_c[rank]    = make_float4(color[gi*3+0], color[gi*3+1], color[gi*3+2], 0.0f);
            __threadfence();                    // release this Gaussian's record
        }
        __syncthreads();

        // device-wide barrier: monotonic epoch counter (replay-safe; all blocks
        // resident in one wave so spinning cannot deadlock). Acquire on one
        // thread + __syncthreads publishes remote writes to the whole block.
        if (tid == 0) {
            unsigned long long ticket = atomicAdd(&g_bar, 1ULL);
            unsigned long long target = (ticket/NBLK + 1ULL) * NBLK;
            unsigned long long cur;
            do {
                asm volatile("ld.acquire.gpu.global.u64 %0, [%1];"
                             : "=l"(cur) : "l"(&g_bar));
            } while (cur < target);
        }
        __syncthreads();
    }

    // ================= Phase 1: cull + compact (2 Gaussians/thread) ==========
    float x0 = (bx*32 + 0.5f)*PIX - tlx;
    float x1 = (bx*32 + 31.5f)*PIX - tlx;
    float y0 = (by*16 + 0.5f)*PIX - tly;
    float y1 = (by*16 + 15.5f)*PIX - tly;

    int g0 = tid*2;
    float4 cu0 = g_cull[g0+0];
    float4 cu1 = g_cull[g0+1];
    unsigned m = 0;
    {
        float cx, cy;
        cx = fminf(fmaxf(cu0.x, x0), x1) - cu0.x;
        cy = fminf(fmaxf(cu0.y, y0), y1) - cu0.y;
        if (cx*cx + cy*cy <= cu0.z) m |= 1u;
        cx = fminf(fmaxf(cu1.x, x0), x1) - cu1.x;
        cy = fminf(fmaxf(cu1.y, y0), y1) - cu1.y;
        if (cx*cx + cy*cy <= cu1.z) m |= 2u;
    }
    int cnt = __popc(m);
    int scan = cnt;
    #pragma unroll
    for (int d = 1; d < 32; d <<= 1) {
        int v = __shfl_up_sync(0xffffffffu, scan, d);
        if (lane >= d) scan += v;
    }
    if (lane == 31) sW[warp] = scan;
    __syncthreads();                             // warp totals
    int ntot = 0;
    {
        #pragma unroll
        for (int w = 0; w < 16; w++) ntot += sW[w];
    }
    int base = 0;
    #pragma unroll
    for (int w = 0; w < 15; w++) if (w < warp) base += sW[w];
    int pos = base + (scan - cnt);
    #pragma unroll
    for (int u = 0; u < 2; u++) {
        if (m & (1u << u)) {
            float4 cu = (u == 0) ? cu0 : cu1;
            float4 qv = g_q[g0+u];
            float4 cv = g_c[g0+u];
            sA[pos] = make_float4(cu.x, cu.y, qv.x, qv.y);
            sB[pos] = make_float4(qv.z, qv.w, cv.x, cv.y);
            ((float*)sC4)[pos] = cv.z;
            pos++;
        }
    }
    if (tid < 8) {                               // zero-alpha dummies (exact no-op)
        sA[ntot+tid] = make_float4(0.f, 0.f, 0.f, 0.f);
        sB[ntot+tid] = make_float4(0.f, -1e30f, 0.f, 0.f);
        ((float*)sC4)[ntot+tid] = 0.f;
    }
    __syncthreads();                             // list published
    int n = (ntot + 3) & ~3;

    // ================= Phase 2: composite (pipelined groups of 4) ============
    float px = (bx*32 + tx + 0.5f)*PIX - tlx;
    float py = (by*16 + ty + 0.5f)*PIX - tly;

    float T = 1.0f, cr = 0.0f, cg = 0.0f, cb = 0.0f;

    float4 A0 = sA[0], A1 = sA[1], A2 = sA[2], A3 = sA[3];
    float4 B0 = sB[0], B1 = sB[1], B2 = sB[2], B3 = sB[3];
    float4 Cv = sC4[0];

    #pragma unroll 2
    for (int i = 0; i < n; i += 4) {
        float4 nA0 = sA[i+4], nA1 = sA[i+5], nA2 = sA[i+6], nA3 = sA[i+7];
        float4 nB0 = sB[i+4], nB1 = sB[i+5], nB2 = sB[i+6], nB3 = sB[i+7];
        float4 nCv = sC4[i/4 + 1];

        float ax[4];
        {
            float dx, dy, qd;
            dx = px - A0.x; dy = py - A0.y;
            qd = dx*(A0.z*dx + A0.w*dy) + (B0.x*dy*dy + B0.y);
            ax[0] = fminf(exp2f(qd), 0.99f);
            dx = px - A1.x; dy = py - A1.y;
            qd = dx*(A1.z*dx + A1.w*dy) + (B1.x*dy*dy + B1.y);
            ax[1] = fminf(exp2f(qd), 0.99f);
            dx = px - A2.x; dy = py - A2.y;
            qd = dx*(A2.z*dx + A2.w*dy) + (B2.x*dy*dy + B2.y);
            ax[2] = fminf(exp2f(qd), 0.99f);
            dx = px - A3.x; dy = py - A3.y;
            qd = dx*(A3.z*dx + A3.w*dy) + (B3.x*dy*dy + B3.y);
            ax[3] = fminf(exp2f(qd), 0.99f);
        }
        float q0 = 1.0f-ax[0], q1 = 1.0f-ax[1], q2 = 1.0f-ax[2], q3 = 1.0f-ax[3];
        float p2 = q0*q1;
        float Tn = T * (p2*(q2*q3));
        if (Tn > T_TH) {
            float t0 = T, t1 = T*q0, t2 = T*p2, t3 = t2*q2;
            float w0v = ax[0]*t0, w1v = ax[1]*t1, w2v = ax[2]*t2, w3v = ax[3]*t3;
            cr = fmaf(w0v, B0.z, cr); cg = fmaf(w0v, B0.w, cg); cb = fmaf(w0v, Cv.x, cb);
            cr = fmaf(w1v, B1.z, cr); cg = fmaf(w1v, B1.w, cg); cb = fmaf(w1v, Cv.y, cb);
            cr = fmaf(w2v, B2.z, cr); cg = fmaf(w2v, B2.w, cg); cb = fmaf(w2v, Cv.z, cb);
            cr = fmaf(w3v, B3.z, cr); cg = fmaf(w3v, B3.w, cg); cb = fmaf(w3v, Cv.w, cb);
            T = Tn;
        } else {
            // crossing group: exact masked sequential (runs at most once)
            float rr[4] = {B0.z, B1.z, B2.z, B3.z};
            float gg[4] = {B0.w, B1.w, B2.w, B3.w};
            float bb[4] = {Cv.x, Cv.y, Cv.z, Cv.w};
            #pragma unroll
            for (int u = 0; u < 4; u++) {
                if (T > T_TH) {
                    float w = ax[u] * T;
                    cr = fmaf(w, rr[u], cr);
                    cg = fmaf(w, gg[u], cg);
                    cb = fmaf(w, bb[u], cb);
                    T *= (1.0f - ax[u]);
                }
            }
            if (T <= T_TH) break;
        }
        A0 = nA0; A1 = nA1; A2 = nA2; A3 = nA3;
        B0 = nB0; B1 = nB1; B2 = nB2; B3 = nB3;
        Cv = nCv;
    }

    out[pi+0] = cr + T*bgr;
    out[pi+1] = cg + T*bgg;
    out[pi+2] = cb + T*bgb;
}

extern "C" void kernel_launch(void* const* d_in, const int* in_sizes, int n_in,
                              void* d_out, int out_size) {
    const float* mean    = (const float*)d_in[0];
    const float* cov     = (const float*)d_in[1];
    const float* color   = (const float*)d_in[2];
    const float* alpha   = (const float*)d_in[3];
    const float* depth   = (const float*)d_in[4];
    const float* bg      = (const float*)d_in[5];
    const float* topleft = (const float*)d_in[6];

    fused_kernel<<<NBLK, 512>>>(mean, cov, color, alpha, depth,
                                bg, topleft, (float*)d_out);
}

// round 11
// speedup vs baseline: 1.3947x; 1.0019x over previous
#include <cuda_runtime.h>

#define IMG 256
#define NG 1024
#define PIX (1.0f/256.0f)
#define T_TH 1e-4f
#define QCUT 10.0f   // cull: quad > 10 => contribution < alpha*e^-5 (boundary-only)
#define EXP_SKIP (-20.0f)  // exp2 arg below this -> contribution < 1e-6, treat as 0
#define NBLK 128     // 8 x 16 tiles of 32x16 px; <= 148 SMs -> all resident

// Sorted + packed per-Gaussian data (device scratch, no allocs)
__device__ float4 g_cull[NG];  // mx, my, rad2, pad
__device__ float4 g_q[NG];     // c00', c01', c11', k'
__device__ float4 g_c[NG];     // cr, cg, cb, pad
__device__ unsigned long long g_bar;   // monotonic barrier counter (zero-init)

// ---------------------------------------------------------------------------
// Single fused kernel: 128 blocks x 512 threads, all resident in one wave.
// Phase 0: each block preps 8 Gaussians (rank sort + packed record), then a
//          device-wide barrier (monotonic epoch counter -> graph-replay safe).
// Phase 1: per-tile cull+compact of all 1024 sorted Gaussians (2 per thread).
// Phase 2: per-pixel front-to-back composite, pipelined groups of 4, with
//          predicated EX2 (skips the MUFU op for far-away Gaussians).
// ---------------------------------------------------------------------------
__global__ void __launch_bounds__(512) fused_kernel(const float* __restrict__ mean,
                                                    const float* __restrict__ cov,
                                                    const float* __restrict__ color,
                                                    const float* __restrict__ alpha,
                                                    const float* __restrict__ depth,
                                                    const float* __restrict__ bg,
                                                    const float* __restrict__ topleft,
                                                    float* __restrict__ out) {
    __shared__ float4 sA[NG+8];        // mx, my, c00', c01'  (aliased by depths in phase 0)
    __shared__ float4 sB[NG+8];        // c11', k', cr, cg
    __shared__ float4 sC4[(NG+8)/4];   // cb, packed
    __shared__ int    sW[16];
    __shared__ int    sRank[8];

    int tid  = threadIdx.x;
    int lane = tid & 31, warp = tid >> 5;

    // tile geometry + background prefetch (hides under barrier wait)
    int bx = blockIdx.x & 7, by = blockIdx.x >> 3;
    float tlx = topleft[0], tly = topleft[1];
    int tx = tid & 31, ty = tid >> 5;
    int pi = ((by*16 + ty)*IMG + bx*32 + tx)*3;
    float bgr = bg[pi+0], bgg = bg[pi+1], bgb = bg[pi+2];

    // ================= Phase 0: prep (8 Gaussians per block) =================
    {
        float4* sd4 = (float4*)sA;              // alias: 1024 depths = 4KB
        const float4* d4g = (const float4*)depth;
        if (tid < 256) sd4[tid] = d4g[tid];
        if (tid < 8)   sRank[tid] = 0;
        __syncthreads();

        int sub = tid >> 6;                     // 0..7 (64 threads per Gaussian)
        int gi  = blockIdx.x*8 + sub;
        float di = ((const float*)sd4)[gi];
        int lo4 = (tid & 63) * 4;               // 16 floats per thread
        int r = 0;
        #pragma unroll
        for (int j4 = 0; j4 < 4; j4++) {
            float4 d = sd4[lo4 + j4];
            int j = (lo4 + j4) * 4;
            r += (d.x < di) || (d.x == di && (j+0) < gi);
            r += (d.y < di) || (d.y == di && (j+1) < gi);
            r += (d.z < di) || (d.z == di && (j+2) < gi);
            r += (d.w < di) || (d.w == di && (j+3) < gi);
        }
        #pragma unroll
        for (int s = 16; s; s >>= 1) r += __shfl_xor_sync(0xffffffffu, r, s);
        if (lane == 0) atomicAdd(&sRank[sub], r);
        __syncthreads();

        if ((tid & 63) == 0) {
            int rank = sRank[sub];
            float a = cov[gi*4+0], b = cov[gi*4+1], c = cov[gi*4+2], d = cov[gi*4+3];
            float det = a*d - b*c;
            const float L2E = 1.4426950408889634f;
            float i00  = d / det;
            float i11  = a / det;
            float ioff = -(b + c) / det;
            float mx = mean[gi*2+0], my = mean[gi*2+1];
            float bs      = 0.5f*(b + c);
            float half_tr = 0.5f*(a + d);
            float disc    = sqrtf(0.25f*(a - d)*(a - d) + bs*bs);
            float al = alpha[gi];
            g_cull[rank] = make_float4(mx, my, QCUT*(half_tr + disc), 0.0f);
            g_q[rank]    = make_float4(-0.5f*L2E*i00, -0.5f*L2E*ioff, -0.5f*L2E*i11,
                                       __log2f(fmaxf(al, 1e-30f)));
            g_c[rank]    = make_float4(color[gi*3+0], color[gi*3+1], color[gi*3+2], 0.0f);
            __threadfence();                    // release this Gaussian's record
        }
        __syncthreads();

        // device-wide barrier (replay-safe; all blocks resident in one wave)
        if (tid == 0) {
            unsigned long long ticket = atomicAdd(&g_bar, 1ULL);
            unsigned long long target = (ticket/NBLK + 1ULL) * NBLK;
            unsigned long long cur;
            do {
                asm volatile("ld.acquire.gpu.global.u64 %0, [%1];"
                             : "=l"(cur) : "l"(&g_bar));
            } while (cur < target);
        }
        __syncthreads();
    }

    // ================= Phase 1: cull + compact (2 Gaussians/thread) ==========
    float x0 = (bx*32 + 0.5f)*PIX - tlx;
    float x1 = (bx*32 + 31.5f)*PIX - tlx;
    float y0 = (by*16 + 0.5f)*PIX - tly;
    float y1 = (by*16 + 15.5f)*PIX - tly;

    int g0 = tid*2;
    float4 cu0 = g_cull[g0+0];
    float4 cu1 = g_cull[g0+1];
    unsigned m = 0;
    {
        float cx, cy;
        cx = fminf(fmaxf(cu0.x, x0), x1) - cu0.x;
        cy = fminf(fmaxf(cu0.y, y0), y1) - cu0.y;
        if (cx*cx + cy*cy <= cu0.z) m |= 1u;
        cx = fminf(fmaxf(cu1.x, x0), x1) - cu1.x;
        cy = fminf(fmaxf(cu1.y, y0), y1) - cu1.y;
        if (cx*cx + cy*cy <= cu1.z) m |= 2u;
    }
    int cnt = __popc(m);
    int scan = cnt;
    #pragma unroll
    for (int d = 1; d < 32; d <<= 1) {
        int v = __shfl_up_sync(0xffffffffu, scan, d);
        if (lane >= d) scan += v;
    }
    if (lane == 31) sW[warp] = scan;
    __syncthreads();                             // warp totals
    int ntot = 0;
    {
        #pragma unroll
        for (int w = 0; w < 16; w++) ntot += sW[w];
    }
    int base = 0;
    #pragma unroll
    for (int w = 0; w < 15; w++) if (w < warp) base += sW[w];
    int pos = base + (scan - cnt);
    #pragma unroll
    for (int u = 0; u < 2; u++) {
        if (m & (1u << u)) {
            float4 cu = (u == 0) ? cu0 : cu1;
            float4 qv = g_q[g0+u];
            float4 cv = g_c[g0+u];
            sA[pos] = make_float4(cu.x, cu.y, qv.x, qv.y);
            sB[pos] = make_float4(qv.z, qv.w, cv.x, cv.y);
            ((float*)sC4)[pos] = cv.z;
            pos++;
        }
    }
    if (tid < 8) {                               // zero-alpha dummies (exact no-op)
        sA[ntot+tid] = make_float4(0.f, 0.f, 0.f, 0.f);
        sB[ntot+tid] = make_float4(0.f, -1e30f, 0.f, 0.f);
        ((float*)sC4)[ntot+tid] = 0.f;
    }
    __syncthreads();                             // list published
    int n = (ntot + 3) & ~3;

    // ================= Phase 2: composite (pipelined groups of 4) ============
    float px = (bx*32 + tx + 0.5f)*PIX - tlx;
    float py = (by*16 + ty + 0.5f)*PIX - tly;

    float T = 1.0f, cr = 0.0f, cg = 0.0f, cb = 0.0f;

    float4 A0 = sA[0], A1 = sA[1], A2 = sA[2], A3 = sA[3];
    float4 B0 = sB[0], B1 = sB[1], B2 = sB[2], B3 = sB[3];
    float4 Cv = sC4[0];

    #pragma unroll 2
    for (int i = 0; i < n; i += 4) {
        float4 nA0 = sA[i+4], nA1 = sA[i+5], nA2 = sA[i+6], nA3 = sA[i+7];
        float4 nB0 = sB[i+4], nB1 = sB[i+5], nB2 = sB[i+6], nB3 = sB[i+7];
        float4 nCv = sC4[i/4 + 1];

        float ax[4];
        {
            float dx, dy, qd;
            // predicated EX2: far-away Gaussians (qd <= -20 -> a < 1e-6) skip
            // the MUFU op entirely, freeing the EX2 pipe.
            dx = px - A0.x; dy = py - A0.y;
            qd = dx*(A0.z*dx + A0.w*dy) + (B0.x*dy*dy + B0.y);
            ax[0] = (qd > EXP_SKIP) ? fminf(exp2f(qd), 0.99f) : 0.0f;
            dx = px - A1.x; dy = py - A1.y;
            qd = dx*(A1.z*dx + A1.w*dy) + (B1.x*dy*dy + B1.y);
            ax[1] = (qd > EXP_SKIP) ? fminf(exp2f(qd), 0.99f) : 0.0f;
            dx = px - A2.x; dy = py - A2.y;
            qd = dx*(A2.z*dx + A2.w*dy) + (B2.x*dy*dy + B2.y);
            ax[2] = (qd > EXP_SKIP) ? fminf(exp2f(qd), 0.99f) : 0.0f;
            dx = px - A3.x; dy = py - A3.y;
            qd = dx*(A3.z*dx + A3.w*dy) + (B3.x*dy*dy + B3.y);
            ax[3] = (qd > EXP_SKIP) ? fminf(exp2f(qd), 0.99f) : 0.0f;
        }
        float q0 = 1.0f-ax[0], q1 = 1.0f-ax[1], q2 = 1.0f-ax[2], q3 = 1.0f-ax[3];
        float p2 = q0*q1;
        float Tn = T * (p2*(q2*q3));
        if (Tn > T_TH) {
            float t0 = T, t1 = T*q0, t2 = T*p2, t3 = t2*q2;
            float w0v = ax[0]*t0, w1v = ax[1]*t1, w2v = ax[2]*t2, w3v = ax[3]*t3;
            cr = fmaf(w0v, B0.z, cr); cg = fmaf(w0v, B0.w, cg); cb = fmaf(w0v, Cv.x, cb);
            cr = fmaf(w1v, B1.z, cr); cg = fmaf(w1v, B1.w, cg); cb = fmaf(w1v, Cv.y, cb);
            cr = fmaf(w2v, B2.z, cr); cg = fmaf(w2v, B2.w, cg); cb = fmaf(w2v, Cv.z, cb);
            cr = fmaf(w3v, B3.z, cr); cg = fmaf(w3v, B3.w, cg); cb = fmaf(w3v, Cv.w, cb);
            T = Tn;
        } else {
            // crossing group: exact masked sequential (runs at most once)
            float rr[4] = {B0.z, B1.z, B2.z, B3.z};
            float gg[4] = {B0.w, B1.w, B2.w, B3.w};
            float bb[4] = {Cv.x, Cv.y, Cv.z, Cv.w};
            #pragma unroll
            for (int u = 0; u < 4; u++) {
                if (T > T_TH) {
                    float w = ax[u] * T;
                    cr = fmaf(w, rr[u], cr);
                    cg = fmaf(w, gg[u], cg);
                    cb = fmaf(w, bb[u], cb);
                    T *= (1.0f - ax[u]);
                }
            }
            if (T <= T_TH) break;
        }
        A0 = nA0; A1 = nA1; A2 = nA2; A3 = nA3;
        B0 = nB0; B1 = nB1; B2 = nB2; B3 = nB3;
        Cv = nCv;
    }

    out[pi+0] = cr + T*bgr;
    out[pi+1] = cg + T*bgg;
    out[pi+2] = cb + T*bgb;
}

extern "C" void kernel_launch(void* const* d_in, const int* in_sizes, int n_in,
                              void* d_out, int out_size) {
    const float* mean    = (const float*)d_in[0];
    const float* cov     = (const float*)d_in[1];
    const float* color   = (const float*)d_in[2];
    const float* alpha   = (const float*)d_in[3];
    const float* depth   = (const float*)d_in[4];
    const float* bg      = (const float*)d_in[5];
    const float* topleft = (const float*)d_in[6];

    fused_kernel<<<NBLK, 512>>>(mean, cov, color, alpha, depth,
                                bg, topleft, (float*)d_out);
}

// round 12
// speedup vs baseline: 1.5605x; 1.1189x over previous
#include <cuda_runtime.h>

#define IMG 256
#define NG 1024
#define PIX (1.0f/256.0f)
#define T_TH 1e-4f
#define QCUT 10.0f   // cull: quad > 10 => contribution < alpha*e^-5 (boundary-only)
#define NBLK 256     // 16 x 16 tiles of 16x16 px; 2 blocks/SM, all resident

// Sorted + packed per-Gaussian data (device scratch, no allocs)
__device__ float4 g_cull[NG];  // mx, my, rad2, pad
__device__ float4 g_q[NG];     // c00', c01', c11', k'
__device__ float4 g_c[NG];     // cr, cg, cb, pad
__device__ unsigned long long g_bar;   // monotonic barrier counter (zero-init)

// ---------------------------------------------------------------------------
// Single fused kernel: 256 blocks x 256 threads, all resident in one wave
// (2 blocks/SM -> averages per-tile cost, halving the slow-tile tail).
// Phase 0: each block preps 4 Gaussians (rank sort + packed record), then a
//          device-wide barrier (monotonic epoch counter -> graph-replay safe).
// Phase 1: per-tile cull+compact of all 1024 sorted Gaussians (4 per thread).
// Phase 2: per-pixel front-to-back composite, pipelined groups of 4.
// ---------------------------------------------------------------------------
__global__ void __launch_bounds__(256) fused_kernel(const float* __restrict__ mean,
                                                    const float* __restrict__ cov,
                                                    const float* __restrict__ color,
                                                    const float* __restrict__ alpha,
                                                    const float* __restrict__ depth,
                                                    const float* __restrict__ bg,
                                                    const float* __restrict__ topleft,
                                                    float* __restrict__ out) {
    __shared__ float4 sA[NG+8];        // mx, my, c00', c01'  (aliased by depths in phase 0)
    __shared__ float4 sB[NG+8];        // c11', k', cr, cg
    __shared__ float4 sC4[(NG+8)/4];   // cb, packed
    __shared__ int    sW[8];
    __shared__ int    sRank[4];

    int tid  = threadIdx.x;
    int lane = tid & 31, warp = tid >> 5;

    // tile geometry + background prefetch (hides under barrier wait)
    int bx = blockIdx.x & 15, by = blockIdx.x >> 4;
    float tlx = topleft[0], tly = topleft[1];
    int tx = tid & 15, ty = tid >> 4;
    int pi = ((by*16 + ty)*IMG + bx*16 + tx)*3;
    float bgr = bg[pi+0], bgg = bg[pi+1], bgb = bg[pi+2];

    // ================= Phase 0: prep (4 Gaussians per block) =================
    {
        float4* sd4 = (float4*)sA;              // alias: 1024 depths = 4KB
        const float4* d4g = (const float4*)depth;
        sd4[tid] = d4g[tid];
        if (tid < 4) sRank[tid] = 0;
        __syncthreads();

        int sub = tid >> 6;                     // 0..3 (64 threads per Gaussian)
        int gi  = blockIdx.x*4 + sub;
        float di = ((const float*)sd4)[gi];
        int lo4 = (tid & 63) * 4;               // 16 floats per thread
        int r = 0;
        #pragma unroll
        for (int j4 = 0; j4 < 4; j4++) {
            float4 d = sd4[lo4 + j4];
            int j = (lo4 + j4) * 4;
            r += (d.x < di) || (d.x == di && (j+0) < gi);
            r += (d.y < di) || (d.y == di && (j+1) < gi);
            r += (d.z < di) || (d.z == di && (j+2) < gi);
            r += (d.w < di) || (d.w == di && (j+3) < gi);
        }
        #pragma unroll
        for (int s = 16; s; s >>= 1) r += __shfl_xor_sync(0xffffffffu, r, s);
        if (lane == 0) atomicAdd(&sRank[sub], r);
        __syncthreads();

        if ((tid & 63) == 0) {
            int rank = sRank[sub];
            float a = cov[gi*4+0], b = cov[gi*4+1], c = cov[gi*4+2], d = cov[gi*4+3];
            float det = a*d - b*c;
            const float L2E = 1.4426950408889634f;
            float i00  = d / det;
            float i11  = a / det;
            float ioff = -(b + c) / det;
            float mx = mean[gi*2+0], my = mean[gi*2+1];
            float bs      = 0.5f*(b + c);
            float half_tr = 0.5f*(a + d);
            float disc    = sqrtf(0.25f*(a - d)*(a - d) + bs*bs);
            float al = alpha[gi];
            g_cull[rank] = make_float4(mx, my, QCUT*(half_tr + disc), 0.0f);
            g_q[rank]    = make_float4(-0.5f*L2E*i00, -0.5f*L2E*ioff, -0.5f*L2E*i11,
                                       __log2f(fmaxf(al, 1e-30f)));
            g_c[rank]    = make_float4(color[gi*3+0], color[gi*3+1], color[gi*3+2], 0.0f);
            __threadfence();                    // release this Gaussian's record
        }
        __syncthreads();

        // device-wide barrier (replay-safe; all blocks resident in one wave)
        if (tid == 0) {
            unsigned long long ticket = atomicAdd(&g_bar, 1ULL);
            unsigned long long target = (ticket/NBLK + 1ULL) * NBLK;
            unsigned long long cur;
            do {
                asm volatile("ld.acquire.gpu.global.u64 %0, [%1];"
                             : "=l"(cur) : "l"(&g_bar));
            } while (cur < target);
        }
        __syncthreads();
    }

    // ================= Phase 1: cull + compact (4 Gaussians/thread) ==========
    float x0 = (bx*16 + 0.5f)*PIX - tlx;
    float x1 = (bx*16 + 15.5f)*PIX - tlx;
    float y0 = (by*16 + 0.5f)*PIX - tly;
    float y1 = (by*16 + 15.5f)*PIX - tly;

    int g0 = tid*4;
    float4 cu0 = g_cull[g0+0];
    float4 cu1 = g_cull[g0+1];
    float4 cu2 = g_cull[g0+2];
    float4 cu3 = g_cull[g0+3];
    unsigned m = 0;
    {
        float cx, cy;
        cx = fminf(fmaxf(cu0.x, x0), x1) - cu0.x;
        cy = fminf(fmaxf(cu0.y, y0), y1) - cu0.y;
        if (cx*cx + cy*cy <= cu0.z) m |= 1u;
        cx = fminf(fmaxf(cu1.x, x0), x1) - cu1.x;
        cy = fminf(fmaxf(cu1.y, y0), y1) - cu1.y;
        if (cx*cx + cy*cy <= cu1.z) m |= 2u;
        cx = fminf(fmaxf(cu2.x, x0), x1) - cu2.x;
        cy = fminf(fmaxf(cu2.y, y0), y1) - cu2.y;
        if (cx*cx + cy*cy <= cu2.z) m |= 4u;
        cx = fminf(fmaxf(cu3.x, x0), x1) - cu3.x;
        cy = fminf(fmaxf(cu3.y, y0), y1) - cu3.y;
        if (cx*cx + cy*cy <= cu3.z) m |= 8u;
    }
    int cnt = __popc(m);
    int scan = cnt;
    #pragma unroll
    for (int d = 1; d < 32; d <<= 1) {
        int v = __shfl_up_sync(0xffffffffu, scan, d);
        if (lane >= d) scan += v;
    }
    if (lane == 31) sW[warp] = scan;
    __syncthreads();                             // warp totals
    int4 wv0 = *(const int4*)&sW[0];
    int4 wv1 = *(const int4*)&sW[4];
    int ntot = (wv0.x + wv0.y + wv0.z + wv0.w) + (wv1.x + wv1.y + wv1.z + wv1.w);
    int base = 0;
    if (warp > 0) base += wv0.x;
    if (warp > 1) base += wv0.y;
    if (warp > 2) base += wv0.z;
    if (warp > 3) base += wv0.w;
    if (warp > 4) base += wv1.x;
    if (warp > 5) base += wv1.y;
    if (warp > 6) base += wv1.z;
    int pos = base + (scan - cnt);
    #pragma unroll
    for (int u = 0; u < 4; u++) {
        if (m & (1u << u)) {
            float4 cu = (u == 0) ? cu0 : (u == 1) ? cu1 : (u == 2) ? cu2 : cu3;
            float4 qv = g_q[g0+u];
            float4 cv = g_c[g0+u];
            sA[pos] = make_float4(cu.x, cu.y, qv.x, qv.y);
            sB[pos] = make_float4(qv.z, qv.w, cv.x, cv.y);
            ((float*)sC4)[pos] = cv.z;
            pos++;
        }
    }
    if (tid < 8) {                               // zero-alpha dummies (exact no-op)
        sA[ntot+tid] = make_float4(0.f, 0.f, 0.f, 0.f);
        sB[ntot+tid] = make_float4(0.f, -1e30f, 0.f, 0.f);
        ((float*)sC4)[ntot+tid] = 0.f;
    }
    __syncthreads();                             // list published
    int n = (ntot + 3) & ~3;

    // ================= Phase 2: composite (pipelined groups of 4) ============
    float px = (bx*16 + tx + 0.5f)*PIX - tlx;
    float py = (by*16 + ty + 0.5f)*PIX - tly;

    float T = 1.0f, cr = 0.0f, cg = 0.0f, cb = 0.0f;

    float4 A0 = sA[0], A1 = sA[1], A2 = sA[2], A3 = sA[3];
    float4 B0 = sB[0], B1 = sB[1], B2 = sB[2], B3 = sB[3];
    float4 Cv = sC4[0];

    #pragma unroll 2
    for (int i = 0; i < n; i += 4) {
        float4 nA0 = sA[i+4], nA1 = sA[i+5], nA2 = sA[i+6], nA3 = sA[i+7];
        float4 nB0 = sB[i+4], nB1 = sB[i+5], nB2 = sB[i+6], nB3 = sB[i+7];
        float4 nCv = sC4[i/4 + 1];

        float ax[4];
        {
            float dx, dy, qd;
            dx = px - A0.x; dy = py - A0.y;
            qd = dx*(A0.z*dx + A0.w*dy) + (B0.x*dy*dy + B0.y);
            ax[0] = fminf(exp2f(qd), 0.99f);
            dx = px - A1.x; dy = py - A1.y;
            qd = dx*(A1.z*dx + A1.w*dy) + (B1.x*dy*dy + B1.y);
            ax[1] = fminf(exp2f(qd), 0.99f);
            dx = px - A2.x; dy = py - A2.y;
            qd = dx*(A2.z*dx + A2.w*dy) + (B2.x*dy*dy + B2.y);
            ax[2] = fminf(exp2f(qd), 0.99f);
            dx = px - A3.x; dy = py - A3.y;
            qd = dx*(A3.z*dx + A3.w*dy) + (B3.x*dy*dy + B3.y);
            ax[3] = fminf(exp2f(qd), 0.99f);
        }
        float q0 = 1.0f-ax[0], q1 = 1.0f-ax[1], q2 = 1.0f-ax[2], q3 = 1.0f-ax[3];
        float p2 = q0*q1;
        float Tn = T * (p2*(q2*q3));
        if (Tn > T_TH) {
            float t0 = T, t1 = T*q0, t2 = T*p2, t3 = t2*q2;
            float w0v = ax[0]*t0, w1v = ax[1]*t1, w2v = ax[2]*t2, w3v = ax[3]*t3;
            cr = fmaf(w0v, B0.z, cr); cg = fmaf(w0v, B0.w, cg); cb = fmaf(w0v, Cv.x, cb);
            cr = fmaf(w1v, B1.z, cr); cg = fmaf(w1v, B1.w, cg); cb = fmaf(w1v, Cv.y, cb);
            cr = fmaf(w2v, B2.z, cr); cg = fmaf(w2v, B2.w, cg); cb = fmaf(w2v, Cv.z, cb);
            cr = fmaf(w3v, B3.z, cr); cg = fmaf(w3v, B3.w, cg); cb = fmaf(w3v, Cv.w, cb);
            T = Tn;
        } else {
            // crossing group: exact masked sequential (runs at most once)
            float rr[4] = {B0.z, B1.z, B2.z, B3.z};
            float gg[4] = {B0.w, B1.w, B2.w, B3.w};
            float bb[4] = {Cv.x, Cv.y, Cv.z, Cv.w};
            #pragma unroll
            for (int u = 0; u < 4; u++) {
                if (T > T_TH) {
                    float w = ax[u] * T;
                    cr = fmaf(w, rr[u], cr);
                    cg = fmaf(w, gg[u], cg);
                    cb = fmaf(w, bb[u], cb);
                    T *= (1.0f - ax[u]);
                }
            }
            if (T <= T_TH) break;
        }
        A0 = nA0; A1 = nA1; A2 = nA2; A3 = nA3;
        B0 = nB0; B1 = nB1; B2 = nB2; B3 = nB3;
        Cv = nCv;
    }

    out[pi+0] = cr + T*bgr;
    out[pi+1] = cg + T*bgg;
    out[pi+2] = cb + T*bgb;
}

extern "C" void kernel_launch(void* const* d_in, const int* in_sizes, int n_in,
                              void* d_out, int out_size) {
    const float* mean    = (const float*)d_in[0];
    const float* cov     = (const float*)d_in[1];
    const float* color   = (const float*)d_in[2];
    const float* alpha   = (const float*)d_in[3];
    const float* depth   = (const float*)d_in[4];
    const float* bg      = (const float*)d_in[5];
    const float* topleft = (const float*)d_in[6];

    fused_kernel<<<NBLK, 256>>>(mean, cov, color, alpha, depth,
                                bg, topleft, (float*)d_out);
}